// round 7
// baseline (speedup 1.0000x reference)
#include <cuda_runtime.h>
#include <cuda_bf16.h>
#include <math.h>
#include <stdint.h>

// ---------------- problem constants ----------------
#define Nn   100000
#define Ee   1600000
#define EN   (Ee + Nn)          // edges incl. self loops = 1,700,000
#define FIN  512
#define FHID 64
#define FOUT 40
#define NEG_SLOPE 0.2f
#define TILES ((Nn + 127) / 128)   // 782

// ---------------- device scratch (no dynamic alloc allowed) ----------------
__device__ __align__(16) float g_h1 [(size_t)Nn * FHID];   // x@W1
__device__ __align__(16) float g_h2 [(size_t)Nn * FOUT];   // fused layer1-out @ W2
__device__ float g_as1[Nn], g_ad1[Nn];
__device__ float g_as2[Nn], g_ad2[Nn];
__device__ int   g_cnt[Nn];
__device__ int   g_off[Nn + 1];
__device__ int   g_cursor[Nn];
__device__ int   g_csr_src[EN];
__device__ int   g_is64;
// global-shift maxima (monotone-encoded floats for unsigned atomicMax)
__device__ unsigned g_mx_as1, g_mx_ad1, g_mx_as2, g_mx_ad2;
// W1 pre-converted: [n][k] K-contiguous bf16 hi/lo, stored as uint2 = 4 bf16 along k
__device__ __align__(16) uint2 g_wbh2[64 * 128];
__device__ __align__(16) uint2 g_wbl2[64 * 128];

#define SCAN_BS   1024
#define SCAN_NBLK ((Nn + SCAN_BS - 1) / SCAN_BS)   // 98
__device__ int g_partials[SCAN_NBLK];

__device__ __forceinline__ uint32_t pack_bf2(float a, float b) {
    __nv_bfloat162 t = __floats2bfloat162_rn(a, b);
    return *reinterpret_cast<uint32_t*>(&t);
}
// monotone float<->uint encoding for atomicMax
__device__ __forceinline__ unsigned fenc(float f) {
    unsigned u = __float_as_uint(f);
    return (u >> 31) ? ~u : (u | 0x80000000u);
}
__device__ __forceinline__ float fdec(unsigned e) {
    return (e >> 31) ? __uint_as_float(e & 0x7FFFFFFFu) : __uint_as_float(~e);
}
__device__ __forceinline__ float leaky(float z) { return z > 0.f ? z : NEG_SLOPE * z; }

// mma.sync m16n8k16 row.col f32.bf16.bf16.f32 (sm_80+ PTX, valid on sm_100)
#define MMA_BF16(c, a, b) \
    asm volatile("mma.sync.aligned.m16n8k16.row.col.f32.bf16.bf16.f32 " \
        "{%0,%1,%2,%3}, {%4,%5,%6,%7}, {%8,%9}, {%0,%1,%2,%3};" \
        : "+f"((c)[0]), "+f"((c)[1]), "+f"((c)[2]), "+f"((c)[3]) \
        : "r"((a)[0]), "r"((a)[1]), "r"((a)[2]), "r"((a)[3]), "r"((b)[0]), "r"((b)[1]))

// ---------------- streams for fork-join overlap (created once, pre-main) ----
static cudaStream_t g_s2;
static cudaEvent_t  g_evFork, g_evJoin;
static struct _StreamInit {
    _StreamInit() {
        cudaStreamCreateWithFlags(&g_s2, cudaStreamNonBlocking);
        cudaEventCreateWithFlags(&g_evFork, cudaEventDisableTiming);
        cudaEventCreateWithFlags(&g_evJoin, cudaEventDisableTiming);
    }
} g_streamInit;

// ---------------- dtype detection ----------------
__global__ void k_detect(const int2* __restrict__ p) {
    __shared__ int flag;
    if (threadIdx.x == 0) flag = 0;
    __syncthreads();
    int nz = 0;
    for (int i = threadIdx.x; i < 1024; i += blockDim.x)
        if (p[i].y != 0) nz = 1;
    if (nz) atomicOr(&flag, 1);
    __syncthreads();
    if (threadIdx.x == 0) g_is64 = (flag == 0) ? 1 : 0;
}

__device__ __forceinline__ int load_edge(const void* ei, long long idx, int is64) {
    int v;
    if (is64) v = (int)((const long long*)ei)[idx];
    else      v = ((const int*)ei)[idx];
    v = v < 0 ? 0 : (v >= Nn ? Nn - 1 : v);
    return v;
}

// ---------------- CSR build ----------------
__global__ void k_init_cnt() {
    int i = blockIdx.x * blockDim.x + threadIdx.x;
    if (i < Nn) g_cnt[i] = 1;
}
__global__ void k_hist(const void* __restrict__ ei) {
    int i = blockIdx.x * blockDim.x + threadIdx.x;
    int is64 = g_is64;
    if (i < Ee) {
        int d = load_edge(ei, (long long)Ee + i, is64);
        atomicAdd(&g_cnt[d], 1);
    }
}
__global__ void k_scan1() {
    __shared__ int sm[SCAN_BS];
    int tid = threadIdx.x;
    int i = blockIdx.x * SCAN_BS + tid;
    int v = (i < Nn) ? g_cnt[i] : 0;
    sm[tid] = v;
    __syncthreads();
    #pragma unroll
    for (int off = 1; off < SCAN_BS; off <<= 1) {
        int t = (tid >= off) ? sm[tid - off] : 0;
        __syncthreads();
        sm[tid] += t;
        __syncthreads();
    }
    int incl = sm[tid];
    if (i < Nn) g_off[i] = incl - v;
    if (tid == SCAN_BS - 1) g_partials[blockIdx.x] = incl;
}
__global__ void k_scan2() {
    if (threadIdx.x == 0 && blockIdx.x == 0) {
        int run = 0;
        for (int b = 0; b < SCAN_NBLK; b++) {
            int t = g_partials[b];
            g_partials[b] = run;
            run += t;
        }
    }
}
__global__ void k_scan3() {
    int i = blockIdx.x * blockDim.x + threadIdx.x;
    if (i < Nn) {
        int o = g_off[i] + g_partials[i / SCAN_BS];
        g_off[i] = o;
        g_cursor[i] = o;
    }
    if (i == 0) g_off[Nn] = EN;
}
__global__ void k_scatter(const void* __restrict__ ei) {
    int i = blockIdx.x * blockDim.x + threadIdx.x;
    if (i >= EN) return;
    int is64 = g_is64;
    int s, d;
    if (i < Ee) {
        s = load_edge(ei, i, is64);
        d = load_edge(ei, (long long)Ee + i, is64);
    } else {
        s = d = i - Ee;
    }
    int pos = atomicAdd(&g_cursor[d], 1);
    if (pos >= 0 && pos < EN) g_csr_src[pos] = s;
}

// ---------------- W1 pre-convert + alpha zero-init + max init ----------------
__global__ void k_convW(const float* __restrict__ W1) {
    int idx = blockIdx.x * blockDim.x + threadIdx.x;
    if (idx == 0) {
        g_mx_as1 = 0u; g_mx_ad1 = 0u; g_mx_as2 = 0u; g_mx_ad2 = 0u;
    }
    if (idx < 64 * 128) {   // n*128 + k4
        int n = idx >> 7, k4 = idx & 127;
        float f[4], lo[4];
        #pragma unroll
        for (int j = 0; j < 4; j++) {
            f[j] = W1[(size_t)(k4 * 4 + j) * FHID + n];
            __nv_bfloat16 hb = __float2bfloat16(f[j]);
            lo[j] = f[j] - __bfloat162float(hb);
        }
        g_wbh2[idx] = make_uint2(pack_bf2(f[0], f[1]), pack_bf2(f[2], f[3]));
        g_wbl2[idx] = make_uint2(pack_bf2(lo[0], lo[1]), pack_bf2(lo[2], lo[3]));
    }
    if (idx < Nn) { g_as1[idx] = 0.f; g_ad1[idx] = 0.f; }
}

// ---------------- GEMM1 via mma.sync bf16 hi/lo split, alpha1 fused ----------
#define ASTR 40   // 32 + 8 pad (bf16) -> 20-word row stride: conflict-free frags
__global__ __launch_bounds__(256) void k_gemm1_mma(const float* __restrict__ x,
                                                   const float* __restrict__ a_s,
                                                   const float* __restrict__ a_d) {
    __shared__ __nv_bfloat16 Ah[128][ASTR], Al[128][ASTR];
    __shared__ __nv_bfloat16 Bh[64][ASTR],  Bl[64][ASTR];
    int tid = threadIdx.x, wid = tid >> 5, lane = tid & 31;
    int warpM = wid & 3, warpN = wid >> 2;     // 4 x 2
    int rowBase = blockIdx.x * 128;
    int g = lane >> 2, tg = lane & 3;

    float acc[2][4][4];
    #pragma unroll
    for (int mt = 0; mt < 2; mt++)
        #pragma unroll
        for (int nt = 0; nt < 4; nt++)
            #pragma unroll
            for (int q = 0; q < 4; q++) acc[mt][nt][q] = 0.f;

    float4 aR[4];
    uint2  bhR[2], blR[2];

#define LOADR(c_) do { \
    _Pragma("unroll") for (int it = 0; it < 4; it++) { \
        int idx = tid + it * 256; int row = idx >> 3, kq = idx & 7; \
        int grow = rowBase + row; \
        aR[it] = (grow < Nn) ? *(const float4*)(x + (size_t)grow * FIN + (c_) * 32 + kq * 4) \
                             : make_float4(0.f, 0.f, 0.f, 0.f); \
    } \
    _Pragma("unroll") for (int it = 0; it < 2; it++) { \
        int idx = tid + it * 256; int n = idx >> 3, j = idx & 7; \
        bhR[it] = g_wbh2[n * 128 + (c_) * 8 + j]; \
        blR[it] = g_wbl2[n * 128 + (c_) * 8 + j]; \
    } } while (0)

#define STS() do { \
    _Pragma("unroll") for (int it = 0; it < 4; it++) { \
        int idx = tid + it * 256; int row = idx >> 3, kq = idx & 7; \
        float4 v = aR[it]; \
        uint32_t h01 = pack_bf2(v.x, v.y), h23 = pack_bf2(v.z, v.w); \
        __nv_bfloat162 hh01 = *reinterpret_cast<__nv_bfloat162*>(&h01); \
        __nv_bfloat162 hh23 = *reinterpret_cast<__nv_bfloat162*>(&h23); \
        uint32_t l01 = pack_bf2(v.x - __bfloat162float(hh01.x), v.y - __bfloat162float(hh01.y)); \
        uint32_t l23 = pack_bf2(v.z - __bfloat162float(hh23.x), v.w - __bfloat162float(hh23.y)); \
        *(uint2*)&Ah[row][kq * 4] = make_uint2(h01, h23); \
        *(uint2*)&Al[row][kq * 4] = make_uint2(l01, l23); \
    } \
    _Pragma("unroll") for (int it = 0; it < 2; it++) { \
        int idx = tid + it * 256; int n = idx >> 3, j = idx & 7; \
        *(uint2*)&Bh[n][j * 4] = bhR[it]; \
        *(uint2*)&Bl[n][j * 4] = blR[it]; \
    } } while (0)

    LOADR(0);
    STS();
    __syncthreads();

    for (int c = 0; c < 16; c++) {
        if (c < 15) LOADR(c + 1);          // prefetch overlaps compute
        #pragma unroll
        for (int kk = 0; kk < 2; kk++) {
            int kb = kk * 16;
            uint32_t aH[2][4], aL[2][4], bH[4][2], bL[4][2];
            #pragma unroll
            for (int mt = 0; mt < 2; mt++) {
                int r0 = warpM * 32 + mt * 16 + g;
                aH[mt][0] = *(const uint32_t*)&Ah[r0    ][kb + tg * 2];
                aH[mt][1] = *(const uint32_t*)&Ah[r0 + 8][kb + tg * 2];
                aH[mt][2] = *(const uint32_t*)&Ah[r0    ][kb + tg * 2 + 8];
                aH[mt][3] = *(const uint32_t*)&Ah[r0 + 8][kb + tg * 2 + 8];
                aL[mt][0] = *(const uint32_t*)&Al[r0    ][kb + tg * 2];
                aL[mt][1] = *(const uint32_t*)&Al[r0 + 8][kb + tg * 2];
                aL[mt][2] = *(const uint32_t*)&Al[r0    ][kb + tg * 2 + 8];
                aL[mt][3] = *(const uint32_t*)&Al[r0 + 8][kb + tg * 2 + 8];
            }
            #pragma unroll
            for (int nt = 0; nt < 4; nt++) {
                int n0 = warpN * 32 + nt * 8 + g;
                bH[nt][0] = *(const uint32_t*)&Bh[n0][kb + tg * 2];
                bH[nt][1] = *(const uint32_t*)&Bh[n0][kb + tg * 2 + 8];
                bL[nt][0] = *(const uint32_t*)&Bl[n0][kb + tg * 2];
                bL[nt][1] = *(const uint32_t*)&Bl[n0][kb + tg * 2 + 8];
            }
            #pragma unroll
            for (int mt = 0; mt < 2; mt++)
                #pragma unroll
                for (int nt = 0; nt < 4; nt++) {
                    MMA_BF16(acc[mt][nt], aH[mt], bH[nt]);
                    MMA_BF16(acc[mt][nt], aL[mt], bH[nt]);
                    MMA_BF16(acc[mt][nt], aH[mt], bL[nt]);
                }
        }
        __syncthreads();
        if (c < 15) {
            STS();
            __syncthreads();
        }
    }

    // epilogue: store h1, fused alpha1 partial dots, and global upper-bound maxima
    float lms = -3.402823e38f, lmd = -3.402823e38f;  // local max of 2*partial
    #pragma unroll
    for (int mt = 0; mt < 2; mt++) {
        int r = rowBase + warpM * 32 + mt * 16 + g;
        float ps0 = 0.f, pd0 = 0.f, ps1 = 0.f, pd1 = 0.f;
        #pragma unroll
        for (int nt = 0; nt < 4; nt++) {
            int cb = warpN * 32 + nt * 8 + tg * 2;
            if (r < Nn)
                *(float2*)(g_h1 + (size_t)r * FHID + cb) =
                    make_float2(acc[mt][nt][0], acc[mt][nt][1]);
            if (r + 8 < Nn)
                *(float2*)(g_h1 + (size_t)(r + 8) * FHID + cb) =
                    make_float2(acc[mt][nt][2], acc[mt][nt][3]);
            float a0s = __ldg(a_s + cb), a1s = __ldg(a_s + cb + 1);
            float a0d = __ldg(a_d + cb), a1d = __ldg(a_d + cb + 1);
            ps0 += acc[mt][nt][0] * a0s + acc[mt][nt][1] * a1s;
            pd0 += acc[mt][nt][0] * a0d + acc[mt][nt][1] * a1d;
            ps1 += acc[mt][nt][2] * a0s + acc[mt][nt][3] * a1s;
            pd1 += acc[mt][nt][2] * a0d + acc[mt][nt][3] * a1d;
        }
        #pragma unroll
        for (int o = 1; o <= 2; o <<= 1) {
            ps0 += __shfl_xor_sync(0xffffffffu, ps0, o);
            pd0 += __shfl_xor_sync(0xffffffffu, pd0, o);
            ps1 += __shfl_xor_sync(0xffffffffu, ps1, o);
            pd1 += __shfl_xor_sync(0xffffffffu, pd1, o);
        }
        if (tg == 0) {
            if (r < Nn)     { atomicAdd(&g_as1[r], ps0);     atomicAdd(&g_ad1[r], pd0); }
            if (r + 8 < Nn) { atomicAdd(&g_as1[r + 8], ps1); atomicAdd(&g_ad1[r + 8], pd1); }
        }
        // as1[r] = sum of 2 warp-halves <= 2*max(half) — track 2*partial as bound
        lms = fmaxf(lms, 2.f * fmaxf(ps0, ps1));
        lmd = fmaxf(lmd, 2.f * fmaxf(pd0, pd1));
    }
    // warp max then block max -> 2 atomicMax per block
    #pragma unroll
    for (int o = 16; o; o >>= 1) {
        lms = fmaxf(lms, __shfl_xor_sync(0xffffffffu, lms, o));
        lmd = fmaxf(lmd, __shfl_xor_sync(0xffffffffu, lmd, o));
    }
    __syncthreads();                       // done with MMA smem; reuse as scratch
    float* red = (float*)&Ah[0][0];
    if (lane == 0) { red[wid] = lms; red[8 + wid] = lmd; }
    __syncthreads();
    if (tid == 0) {
        float ms = red[0], md = red[8];
        #pragma unroll
        for (int w = 1; w < 8; w++) { ms = fmaxf(ms, red[w]); md = fmaxf(md, red[8 + w]); }
        atomicMax(&g_mx_as1, fenc(ms));
        atomicMax(&g_mx_ad1, fenc(md));
    }
#undef LOADR
#undef STS
}

// ------- fused: layer-1 aggregation + relu + GEMM2 + alpha2 (+max as2/ad2) ---
// 8 warps/block, one node per warp; grid = Nn/8 = 12500 exact.
__global__ __launch_bounds__(256) void k_agg1g2(const float* __restrict__ b1,
                                                const float* __restrict__ W2,
                                                const float* __restrict__ a_s2,
                                                const float* __restrict__ a_d2) {
    __shared__ float W2s[FHID * FOUT];       // [k][c]
    __shared__ float s_as[FOUT], s_ad[FOUT], b1s[FHID];
    __shared__ float ws[8][FHID];
    __shared__ float redS[8], redD[8];
    int tid = threadIdx.x, wid = tid >> 5, lane = tid & 31;

    for (int t = tid; t < FHID * FOUT; t += 256) W2s[t] = W2[t];
    if (tid < FOUT) { s_as[tid] = a_s2[tid]; s_ad[tid] = a_d2[tid]; }
    if (tid < FHID) b1s[tid] = b1[tid];
    __syncthreads();

    int d = blockIdx.x * 8 + wid;
    int beg = __ldg(&g_off[d]), end = __ldg(&g_off[d + 1]);
    float add = g_ad1[d];
    float m1 = leaky(fdec(g_mx_as1) + fdec(g_mx_ad1));   // global upper bound

    // single-pass aggregation (2 features per lane)
    float acc0 = 0.f, acc1 = 0.f, ssum = 0.f;
    for (int e = beg; e < end; ++e) {
        int s = __ldg(&g_csr_src[e]);
        s = (unsigned)s >= Nn ? 0 : s;
        float l = leaky(__ldg(&g_as1[s]) + add);
        float w = __expf(l - m1);
        ssum += w;
        float2 hv = *(const float2*)(g_h1 + (size_t)s * FHID + 2 * lane);
        acc0 += w * hv.x;
        acc1 += w * hv.y;
    }
    float inv = 1.f / ssum;
    ws[wid][2 * lane]     = fmaxf(acc0 * inv + b1s[2 * lane], 0.f);
    ws[wid][2 * lane + 1] = fmaxf(acc1 * inv + b1s[2 * lane + 1], 0.f);
    __syncwarp();

    // matvec 64x40: lane computes output c=lane (and c=lane+32 when lane<8)
    const float* row = ws[wid];
    int c2 = lane + 32;
    float h0 = 0.f, h1v = 0.f;
    #pragma unroll
    for (int k = 0; k < FHID; k++) {
        float rv = row[k];
        h0 += rv * W2s[k * FOUT + lane];
        if (c2 < FOUT) h1v += rv * W2s[k * FOUT + c2];
    }
    float* orow = g_h2 + (size_t)d * FOUT;
    if (lane < FOUT) orow[lane] = h0;
    if (c2 < FOUT) orow[c2] = h1v;

    // alpha2 = h2 . a_src2 / a_dst2 (warp-reduce partials)
    float ps = (lane < FOUT) ? h0 * s_as[lane] : 0.f;
    float pd = (lane < FOUT) ? h0 * s_ad[lane] : 0.f;
    if (c2 < FOUT) { ps += h1v * s_as[c2]; pd += h1v * s_ad[c2]; }
    #pragma unroll
    for (int o = 16; o; o >>= 1) {
        ps += __shfl_xor_sync(0xffffffffu, ps, o);
        pd += __shfl_xor_sync(0xffffffffu, pd, o);
    }
    if (lane == 0) {
        g_as2[d] = ps;
        g_ad2[d] = pd;
        redS[wid] = ps;
        redD[wid] = pd;
    }
    __syncthreads();
    if (tid == 0) {
        float ms = redS[0], md = redD[0];
        #pragma unroll
        for (int w = 1; w < 8; w++) { ms = fmaxf(ms, redS[w]); md = fmaxf(md, redD[w]); }
        atomicMax(&g_mx_as2, fenc(ms));
        atomicMax(&g_mx_ad2, fenc(md));
    }
}

// ---------------- layer-2 aggregation + bias + log_softmax (single pass) -----
__global__ __launch_bounds__(256) void k_agg2(const float* __restrict__ b2,
                                              float* __restrict__ out) {
    int warp = (blockIdx.x * blockDim.x + threadIdx.x) >> 5;
    int lane = threadIdx.x & 31;
    int d = warp;
    int beg = __ldg(&g_off[d]), end = __ldg(&g_off[d + 1]);
    float add = g_ad2[d];
    float m2 = leaky(fdec(g_mx_as2) + fdec(g_mx_ad2));

    float acc0 = 0.f, acc1 = 0.f, ssum = 0.f;
    for (int e = beg; e < end; ++e) {
        int s = __ldg(&g_csr_src[e]);
        s = (unsigned)s >= Nn ? 0 : s;
        float l = leaky(__ldg(&g_as2[s]) + add);
        float w = __expf(l - m2);
        ssum += w;
        const float* hrow = g_h2 + (size_t)s * FOUT;
        acc0 += w * hrow[lane];
        if (lane < FOUT - 32) acc1 += w * hrow[32 + lane];
    }
    float inv = 1.f / ssum;
    float v0 = acc0 * inv + b2[lane];
    float v1 = (lane < FOUT - 32) ? acc1 * inv + b2[32 + lane] : -3.402823e38f;

    // log_softmax over the 40 values held by the warp
    float mx = fmaxf(v0, v1);
    #pragma unroll
    for (int o = 16; o; o >>= 1) mx = fmaxf(mx, __shfl_xor_sync(0xffffffffu, mx, o));
    float se = __expf(v0 - mx) + ((lane < FOUT - 32) ? __expf(v1 - mx) : 0.f);
    #pragma unroll
    for (int o = 16; o; o >>= 1) se += __shfl_xor_sync(0xffffffffu, se, o);
    float lse = logf(se);

    float* orow = out + (size_t)d * FOUT;
    orow[lane] = v0 - mx - lse;
    if (lane < FOUT - 32) orow[32 + lane] = v1 - mx - lse;
}

// ---------------- launcher ----------------
extern "C" void kernel_launch(void* const* d_in, const int* in_sizes, int n_in,
                              void* d_out, int out_size) {
    const float* x      = (const float*)d_in[0];
    const void*  ei     = d_in[1];
    const float* W1     = (const float*)d_in[2];
    const float* a_src1 = (const float*)d_in[3];
    const float* a_dst1 = (const float*)d_in[4];
    const float* b1     = (const float*)d_in[5];
    const float* W2     = (const float*)d_in[6];
    const float* a_src2 = (const float*)d_in[7];
    const float* a_dst2 = (const float*)d_in[8];
    const float* b2     = (const float*)d_in[9];
    float* out = (float*)d_out;

    // detect dtype on main stream, then fork CSR chain onto side stream
    k_detect<<<1, 256>>>((const int2*)ei);
    cudaEventRecord(g_evFork, 0);
    cudaStreamWaitEvent(g_s2, g_evFork, 0);

    // side stream: CSR build (independent of GEMM1)
    k_init_cnt<<<(Nn + 255) / 256, 256, 0, g_s2>>>();
    k_hist<<<(Ee + 255) / 256, 256, 0, g_s2>>>(ei);
    k_scan1<<<SCAN_NBLK, SCAN_BS, 0, g_s2>>>();
    k_scan2<<<1, 32, 0, g_s2>>>();
    k_scan3<<<(Nn + 255) / 256, 256, 0, g_s2>>>();
    k_scatter<<<(EN + 255) / 256, 256, 0, g_s2>>>(ei);
    cudaEventRecord(g_evJoin, g_s2);

    // main stream: W1 convert + init, then GEMM1 with fused alpha1 + maxima
    k_convW<<<(Nn + 255) / 256, 256>>>(W1);
    k_gemm1_mma<<<TILES, 256>>>(x, a_src1, a_dst1);

    // join: fused agg1+gemm2 needs CSR + gemm1 results
    cudaStreamWaitEvent(0, g_evJoin, 0);
    k_agg1g2<<<Nn / 8, 256>>>(b1, W2, a_src2, a_dst2);

    // layer-2 aggregation + log_softmax
    k_agg2<<<Nn / 8, 256>>>(b2, out);
}